// round 1
// baseline (speedup 1.0000x reference)
#include <cuda_runtime.h>
#include <cstdint>
#include <cstddef>

#define N_NODES  16384
#define IN_DIM   512
#define E_DIM    256
#define BR       32              // rows per block
#define KB       16              // K chunk
#define WSP      17              // ws row stride (odd -> conflict-free b loads)
#define NTHREADS 256
#define NBLOCKS  (N_NODES / BR)  // 512

__device__ __forceinline__ unsigned long long pk2(float lo, float hi) {
    unsigned long long r;
    asm("mov.b64 %0, {%1, %2};" : "=l"(r) : "f"(lo), "f"(hi));
    return r;
}
__device__ __forceinline__ void upk2(unsigned long long v, float& lo, float& hi) {
    asm("mov.b64 {%0, %1}, %2;" : "=f"(lo), "=f"(hi) : "l"(v));
}
__device__ __forceinline__ unsigned long long fma2(unsigned long long a,
                                                   unsigned long long b,
                                                   unsigned long long c) {
    unsigned long long d;
    asm("fma.rn.f32x2 %0, %1, %2, %3;" : "=l"(d) : "l"(a), "l"(b), "l"(c));
    return d;
}

__global__ void __launch_bounds__(NTHREADS, 2)
fused_gcn_kernel(const float* __restrict__ adj,
                 const float* __restrict__ x,
                 const float* __restrict__ W,
                 float* __restrict__ out)
{
    __shared__ float ws[E_DIM * WSP];   // 256*17*4 = 17408 B
    __shared__ float d_s[BR];

    const int tid  = threadIdx.x;
    const int wid  = tid >> 5;
    const int lane = tid & 31;
    const int r0   = blockIdx.x * BR;

    // ---------------- Phase 1: row sums of adj (streaming, evict-first) ----
    {
        const int rb = r0 + (wid << 2);
        float s0 = 0.f, s1 = 0.f, s2 = 0.f, s3 = 0.f;
        const float4* p0 = reinterpret_cast<const float4*>(adj + (size_t)(rb + 0) * N_NODES) + lane;
        const float4* p1 = reinterpret_cast<const float4*>(adj + (size_t)(rb + 1) * N_NODES) + lane;
        const float4* p2 = reinterpret_cast<const float4*>(adj + (size_t)(rb + 2) * N_NODES) + lane;
        const float4* p3 = reinterpret_cast<const float4*>(adj + (size_t)(rb + 3) * N_NODES) + lane;
        #pragma unroll 4
        for (int it = 0; it < N_NODES / 128; ++it) {
            const int off = it * 32;
            float4 v0 = __ldcs(p0 + off);
            float4 v1 = __ldcs(p1 + off);
            float4 v2 = __ldcs(p2 + off);
            float4 v3 = __ldcs(p3 + off);
            s0 += (v0.x + v0.y) + (v0.z + v0.w);
            s1 += (v1.x + v1.y) + (v1.z + v1.w);
            s2 += (v2.x + v2.y) + (v2.z + v2.w);
            s3 += (v3.x + v3.y) + (v3.z + v3.w);
        }
        #pragma unroll
        for (int o = 16; o; o >>= 1) {
            s0 += __shfl_xor_sync(0xffffffffu, s0, o);
            s1 += __shfl_xor_sync(0xffffffffu, s1, o);
            s2 += __shfl_xor_sync(0xffffffffu, s2, o);
            s3 += __shfl_xor_sync(0xffffffffu, s3, o);
        }
        if (lane == 0) {
            d_s[(wid << 2) + 0] = 1.f / (s0 + 1.f) + 1.f;
            d_s[(wid << 2) + 1] = 1.f / (s1 + 1.f) + 1.f;
            d_s[(wid << 2) + 2] = 1.f / (s2 + 1.f) + 1.f;
            d_s[(wid << 2) + 3] = 1.f / (s3 + 1.f) + 1.f;
        }
    }
    __syncthreads();

    // ---------------- Phase 2: out_tile = relu(x_tile @ W^T) * d ----------
    float dv[4];
    #pragma unroll
    for (int i = 0; i < 4; ++i) dv[i] = d_s[(wid << 2) + i];

    const float* xrow[4];
    #pragma unroll
    for (int i = 0; i < 4; ++i)
        xrow[i] = x + (size_t)(r0 + (wid << 2) + i) * IN_DIM;

    unsigned long long acc[4][4];
    #pragma unroll
    for (int i = 0; i < 4; ++i)
        #pragma unroll
        for (int j = 0; j < 4; ++j) acc[i][j] = 0ULL;  // (0.f, 0.f)

    for (int kc = 0; kc < IN_DIM; kc += KB) {
        __syncthreads();  // previous chunk of ws fully consumed
        // Load W[0:256][kc:kc+16] into ws[e*WSP + kk]. Coalesced LDG.128.
        {
            const int e_lo = tid >> 2;          // 0..63
            const int j4   = (tid & 3) << 2;    // 0,4,8,12
            #pragma unroll
            for (int pass = 0; pass < 4; ++pass) {
                const int e = e_lo + (pass << 6);
                const float4 w4 = *reinterpret_cast<const float4*>(
                    W + (size_t)e * IN_DIM + kc + j4);
                float* dst = &ws[e * WSP + j4];
                dst[0] = w4.x; dst[1] = w4.y; dst[2] = w4.z; dst[3] = w4.w;
            }
        }
        __syncthreads();

        #pragma unroll
        for (int q = 0; q < 4; ++q) {
            float ax[4][4];
            #pragma unroll
            for (int i = 0; i < 4; ++i) {
                const float4 v = __ldcs(reinterpret_cast<const float4*>(
                    xrow[i] + kc + (q << 2)));
                ax[i][0] = v.x; ax[i][1] = v.y; ax[i][2] = v.z; ax[i][3] = v.w;
            }
            #pragma unroll
            for (int t = 0; t < 4; ++t) {
                const int kk = (q << 2) + t;
                float b[8];
                #pragma unroll
                for (int j = 0; j < 8; ++j)       // conflict-free: odd stride 17
                    b[j] = ws[(lane + (j << 5)) * WSP + kk];
                unsigned long long b2[4];
                #pragma unroll
                for (int j = 0; j < 4; ++j)
                    b2[j] = pk2(b[2 * j], b[2 * j + 1]);
                #pragma unroll
                for (int i = 0; i < 4; ++i) {
                    const unsigned long long a2 = pk2(ax[i][t], ax[i][t]);
                    #pragma unroll
                    for (int j = 0; j < 4; ++j)
                        acc[i][j] = fma2(a2, b2[j], acc[i][j]);
                }
            }
        }
    }

    // Epilogue: relu then scale by d (valid since d > 0), coalesced stores.
    #pragma unroll
    for (int i = 0; i < 4; ++i) {
        const size_t obase = (size_t)(r0 + (wid << 2) + i) * E_DIM;
        const float d = dv[i];
        #pragma unroll
        for (int j = 0; j < 4; ++j) {
            float lo, hi;
            upk2(acc[i][j], lo, hi);
            out[obase + lane + ((2 * j) << 5)]     = d * fmaxf(lo, 0.f);
            out[obase + lane + ((2 * j + 1) << 5)] = d * fmaxf(hi, 0.f);
        }
    }
}

extern "C" void kernel_launch(void* const* d_in, const int* in_sizes, int n_in,
                              void* d_out, int out_size) {
    (void)in_sizes; (void)n_in; (void)out_size;
    const float* adj = (const float*)d_in[0];
    const float* x   = (const float*)d_in[1];
    const float* W   = (const float*)d_in[2];
    float* out       = (float*)d_out;
    fused_gcn_kernel<<<NBLOCKS, NTHREADS>>>(adj, x, W, out);
}